// round 15
// baseline (speedup 1.0000x reference)
#include <cuda_runtime.h>
#include <cuda_fp16.h>
#include <math.h>
#include <stdint.h>

#define N 8192
#define CLS 8
#define DIM 256
#define INV_T 14.285714285714286f
#define EXP_SCALE 20.60992915555662f   /* (1/0.07) * log2(e) */
#define ALPHA 0.3f
#define LSM 0.1f
#define NT_ROW 64
#define NCHUNK 128

// ---------------- scratch ------------------------------------------------------------
__device__ float g_embn[N * DIM];
__device__ uint16_t g_embq[N * DIM / 2];
__device__ float g_clsum_part[NCHUNK * CLS * DIM];
__device__ float g_clcnt_part[NCHUNK * CLS];
__device__ float g_clsum[CLS * DIM];
__device__ float g_clcnt[CLS];
__device__ float g_Zp[N * NT_ROW];
__device__ float g_con[N];
__device__ float g_ce_part[16 * 16];
__device__ unsigned g_cls_cnt;        // monotonic; last of 64 partial writers finalizes
__device__ unsigned g_fin_cnt;        // monotonic; last of 1024 k_con blocks finalizes

// ---------------- helpers ------------------------------------------------------------
__device__ __forceinline__ uint32_t smem_u32(const void* p) {
    uint32_t a;
    asm("{ .reg .u64 t; cvta.to.shared.u64 t, %1; cvt.u32.u64 %0, t; }" : "=r"(a) : "l"(p));
    return a;
}
__device__ __forceinline__ float ex2f(float x) {
    float y; asm("ex2.approx.f32 %0, %1;" : "=f"(y) : "f"(x)); return y;
}
__device__ __forceinline__ void cp16(uint32_t dst, const void* src) {
    asm volatile("cp.async.cg.shared.global [%0], [%1], 16;" :: "r"(dst), "l"(src));
}
#define CP_COMMIT() asm volatile("cp.async.commit_group;" ::: "memory")
#define CP_WAIT0()  asm volatile("cp.async.wait_group 0;" ::: "memory")

__device__ __forceinline__ void ldsm4(uint32_t& r0, uint32_t& r1, uint32_t& r2, uint32_t& r3,
                                      uint32_t addr) {
    asm volatile("ldmatrix.sync.aligned.m8n8.x4.shared.b16 {%0,%1,%2,%3}, [%4];"
                 : "=r"(r0), "=r"(r1), "=r"(r2), "=r"(r3) : "r"(addr));
}
__device__ __forceinline__ void mma_fp8(float* c, uint32_t a0, uint32_t a1, uint32_t a2,
                                        uint32_t a3, uint32_t b0, uint32_t b1) {
    asm volatile("mma.sync.aligned.m16n8k32.row.col.f32.e4m3.e4m3.f32 "
                 "{%0,%1,%2,%3}, {%4,%5,%6,%7}, {%8,%9}, {%0,%1,%2,%3};"
                 : "+f"(c[0]), "+f"(c[1]), "+f"(c[2]), "+f"(c[3])
                 : "r"(a0), "r"(a1), "r"(a2), "r"(a3), "r"(b0), "r"(b1));
}
__device__ __forceinline__ uint16_t f2e4m3x2(float hi, float lo) {
    uint16_t r;
    asm("cvt.rn.satfinite.e4m3x2.f32 %0, %1, %2;" : "=h"(r) : "f"(hi), "f"(lo));
    return r;
}
__device__ __forceinline__ float2 e4m3x2_to_f2(uint32_t p) {
    uint32_t h;
    float lo, hi;
    asm("cvt.rn.f16x2.e4m3x2 %0, %1;" : "=r"(h) : "h"((uint16_t)p));
    asm("{ .reg .f16 a, b; mov.b32 {a, b}, %2; cvt.f32.f16 %0, a; cvt.f32.f16 %1, b; }"
        : "=f"(lo), "=f"(hi) : "r"(h));
    return make_float2(lo, hi);
}

// ---------------- 1) normalize + fp8 convert -----------------------------------------
__global__ void k_norm(const float* __restrict__ emb) {
    int w = threadIdx.x >> 5, lane = threadIdx.x & 31;
    int row = blockIdx.x * 8 + w;
    const float4* src = (const float4*)(emb + (size_t)row * DIM);
    float4 v0 = src[lane * 2], v1 = src[lane * 2 + 1];
    float ss = v0.x * v0.x + v0.y * v0.y + v0.z * v0.z + v0.w * v0.w +
               v1.x * v1.x + v1.y * v1.y + v1.z * v1.z + v1.w * v1.w;
#pragma unroll
    for (int off = 16; off > 0; off >>= 1) ss += __shfl_xor_sync(0xFFFFFFFF, ss, off);
    float inv = 1.0f / fmaxf(sqrtf(ss), 1e-12f);
    v0.x *= inv; v0.y *= inv; v0.z *= inv; v0.w *= inv;
    v1.x *= inv; v1.y *= inv; v1.z *= inv; v1.w *= inv;
    float4* dst = (float4*)(g_embn + (size_t)row * DIM);
    dst[lane * 2] = v0;
    dst[lane * 2 + 1] = v1;
    uint32_t u0 = (uint32_t)f2e4m3x2(v0.y, v0.x) | ((uint32_t)f2e4m3x2(v0.w, v0.z) << 16);
    uint32_t u1 = (uint32_t)f2e4m3x2(v1.y, v1.x) | ((uint32_t)f2e4m3x2(v1.w, v1.z) << 16);
    *(uint2*)(g_embq + (size_t)row * 128 + lane * 4) = make_uint2(u0, u1);
}

// ---------------- 2) HOT: symmetric Z + side jobs + cls finalize fold ---------------
#define SAB 272
#define A_BYTES (128 * SAB)
#define AS(p) ((p) * A_BYTES)
#define BS(b) ((2 + (b)) * A_BYTES)
#define RED_OFF (4 * A_BYTES)
#define RED_PAR 4096
#define SMEM_TOTAL (RED_OFF + 2 * RED_PAR)

__device__ __forceinline__ void load_tile_async(uint32_t sbase, int grow0, int tid) {
    const char* src = (const char*)g_embq + (size_t)grow0 * 256;
#pragma unroll
    for (int i = 0; i < 4; i++) {
        int idx = tid + i * 512;
        int row = idx >> 4, cb = idx & 15;
        cp16(sbase + row * SAB + cb * 16, src + (size_t)row * 256 + cb * 16);
    }
}

__global__ void __launch_bounds__(512, 1) k_sim_sym(const float* __restrict__ logits,
                                                   const int* __restrict__ tgt) {
    extern __shared__ char smem[];
    uint32_t sb = smem_u32(smem);
    int tid = threadIdx.x;
    int lane = tid & 31;
    int wid = tid >> 5;
    int wx = wid & 3;
    int wy = wid >> 2;
    int bid = blockIdx.x;

    int base = bid * 14 + (bid < 8 ? bid : 8);
    int cnt = 14 + (bid < 8 ? 1 : 0);

    int idx = base, I = 0;
    while (idx >= NT_ROW - I) { idx -= NT_ROW - I; I++; }
    int J = I + idx;

    int ap = 0;
    load_tile_async(sb + AS(0), I * 128, tid);
    if (J != I) load_tile_async(sb + BS(0), J * 128, tid);
    CP_COMMIT();

    if (bid >= 8 && bid < 72) {
        int half = tid >> 8;
        int d = tid & 255;
        int chunk = (bid - 8) * 2 + half;
        int i0 = chunk * 64;
        float a[CLS];
#pragma unroll
        for (int c = 0; c < CLS; c++) a[c] = 0.f;
        for (int k = 0; k < 64; k++) {
            int tg = tgt[i0 + k];
            float v = g_embn[(size_t)(i0 + k) * DIM + d];
#pragma unroll
            for (int c = 0; c < CLS; c++) a[c] += (tg == c) ? v : 0.f;
        }
#pragma unroll
        for (int c = 0; c < CLS; c++) g_clsum_part[(chunk * CLS + c) * DIM + d] = a[c];
        if (d == 0) {
            int cc[CLS];
#pragma unroll
            for (int c = 0; c < CLS; c++) cc[c] = 0;
            for (int k = 0; k < 64; k++) {
                int tg = tgt[i0 + k];
#pragma unroll
                for (int c = 0; c < CLS; c++) cc[c] += (tg == c);
            }
#pragma unroll
            for (int c = 0; c < CLS; c++) g_clcnt_part[chunk * CLS + c] = (float)cc[c];
        }

        // ---- folded class-sum finalize: last of the 64 partial-writing CTAs ----
        __syncthreads();                 // block's partial writes complete
        __shared__ unsigned s_last;
        if (tid == 0) {
            __threadfence();             // publish partials before counting
            unsigned old = atomicAdd(&g_cls_cnt, 1u);
            s_last = ((old & 63u) == 63u) ? 1u : 0u;
        }
        __syncthreads();
        if (s_last) {
            // all 64 CTAs' partials visible (each fenced before its add)
            for (int item = tid; item < CLS * DIM; item += 512) {
                int c = item >> 8, d2 = item & 255;
                float s = 0.f;
                for (int b = 0; b < NCHUNK; b++) s += g_clsum_part[(b * CLS + c) * DIM + d2];
                g_clsum[c * DIM + d2] = s;
            }
            if (tid < CLS) {
                float cn = 0.f;
                for (int b = 0; b < NCHUNK; b++) cn += g_clcnt_part[b * CLS + tid];
                g_clcnt[tid] = cn;
            }
        }
    } else if (bid >= 72 && bid < 88) {
        int chunk = bid - 72;
        int i = chunk * 512 + tid;
        const float4* p = (const float4*)(logits + (size_t)i * CLS);
        float4 u = p[0], w = p[1];
        float x[CLS] = {u.x, u.y, u.z, u.w, w.x, w.y, w.z, w.w};
        float m = x[0];
#pragma unroll
        for (int j = 1; j < CLS; j++) m = fmaxf(m, x[j]);
        float se = 0.f;
#pragma unroll
        for (int j = 0; j < CLS; j++) se += expf(x[j] - m);
        float lse = m + logf(se);
        int tg = tgt[i];
        float nll = lse - x[tg];
        float sx = 0.f;
#pragma unroll
        for (int j = 0; j < CLS; j++) sx += x[j];
        float smooth = lse - sx * (1.0f / CLS);
        float ce = (1.0f - LSM) * nll + LSM * smooth;
        float pt = expf(-ce);
        float omp = 1.0f - pt;
        float focal = omp * omp * ce;
#pragma unroll
        for (int off = 16; off > 0; off >>= 1)
            focal += __shfl_xor_sync(0xFFFFFFFF, focal, off);
        if (lane == 0) g_ce_part[chunk * 16 + wid] = focal;
    }

    CP_WAIT0();
    __syncthreads();

    uint32_t a_lane = (wy * 32 + (lane & 15)) * SAB + ((lane >> 4) << 4);
    uint32_t b_lane = ((lane & 7) + ((lane >> 4) << 3)) * SAB + (((lane >> 3) & 1) << 4) +
                      (wx * 32) * SAB;

    const float EXP_DIAG = expf(INV_T);
    int lrl0 = wy * 32 + (lane >> 2);
    int lcb0 = wx * 32 + (lane & 3) * 2;

    float prev[2][4][4];
    int Ip = 0, Jp = 0;
    bool dtp = false;

    for (int t = 0; t < cnt; t++) {
        int I1 = I, J1 = J + 1;
        if (J1 == NT_ROW) { I1 = I + 1; J1 = I1; }
        bool havenext = (t + 1 < cnt);
        int apn = ap;
        if (havenext) {
            if (I1 != I) {
                apn = ap ^ 1;
                load_tile_async(sb + AS(apn), I1 * 128, tid);
            }
            if (J1 != I1) {
                load_tile_async(sb + BS((t + 1) & 1), J1 * 128, tid);
            }
            CP_COMMIT();
        }

        bool dt = (I == J);
        uint32_t a_addr = sb + AS(ap) + a_lane;
        uint32_t bbuf = (dt ? (sb + AS(ap)) : (sb + BS(t & 1))) + b_lane;

        float acc[2][4][4];
#pragma unroll
        for (int mt = 0; mt < 2; mt++)
#pragma unroll
            for (int nt = 0; nt < 4; nt++)
#pragma unroll
                for (int q = 0; q < 4; q++) acc[mt][nt][q] = 0.f;

        float rlo[2] = {0.f, 0.f}, rhi[2] = {0.f, 0.f};
        float cp0[4] = {0.f, 0.f, 0.f, 0.f}, cp1[4] = {0.f, 0.f, 0.f, 0.f};

#pragma unroll
        for (int ks = 0; ks < 8; ks++) {
            uint32_t koff = ks * 32;
            uint32_t a0[4], a1[4];
            ldsm4(a0[0], a0[1], a0[2], a0[3], a_addr + koff);
            ldsm4(a1[0], a1[1], a1[2], a1[3], a_addr + 16 * SAB + koff);
            uint32_t bfr[2][4];
#pragma unroll
            for (int p = 0; p < 2; p++)
                ldsm4(bfr[p][0], bfr[p][1], bfr[p][2], bfr[p][3],
                      bbuf + (p * 16) * SAB + koff);
#pragma unroll
            for (int nt = 0; nt < 4; nt++) {
                uint32_t bb0 = bfr[nt >> 1][(nt & 1) * 2];
                uint32_t bb1 = bfr[nt >> 1][(nt & 1) * 2 + 1];
                mma_fp8(acc[0][nt], a0[0], a0[1], a0[2], a0[3], bb0, bb1);
                mma_fp8(acc[1][nt], a1[0], a1[1], a1[2], a1[3], bb0, bb1);
            }
            if (t > 0) {
                int mt = ks & 1, nt = ks >> 1;
                int lr = lrl0 + mt * 16;
                int lc = lcb0 + nt * 8;
                float v0 = (dtp && lc == lr)         ? EXP_DIAG : ex2f(prev[mt][nt][0] * EXP_SCALE);
                float v1 = (dtp && lc + 1 == lr)     ? EXP_DIAG : ex2f(prev[mt][nt][1] * EXP_SCALE);
                float v2 = (dtp && lc == lr + 8)     ? EXP_DIAG : ex2f(prev[mt][nt][2] * EXP_SCALE);
                float v3 = (dtp && lc + 1 == lr + 8) ? EXP_DIAG : ex2f(prev[mt][nt][3] * EXP_SCALE);
                rlo[mt] += v0 + v1;
                rhi[mt] += v2 + v3;
                cp0[nt] += v0 + v2;
                cp1[nt] += v1 + v3;
            }
        }

        if (t > 0) {
            float* red_row = (float*)(smem + RED_OFF + ((t - 1) & 1) * RED_PAR);
            float* red_col = red_row + 512;
#pragma unroll
            for (int mt = 0; mt < 2; mt++) {
                rlo[mt] += __shfl_xor_sync(0xFFFFFFFF, rlo[mt], 1);
                rlo[mt] += __shfl_xor_sync(0xFFFFFFFF, rlo[mt], 2);
                rhi[mt] += __shfl_xor_sync(0xFFFFFFFF, rhi[mt], 1);
                rhi[mt] += __shfl_xor_sync(0xFFFFFFFF, rhi[mt], 2);
            }
#pragma unroll
            for (int nt = 0; nt < 4; nt++) {
                cp0[nt] += __shfl_xor_sync(0xFFFFFFFF, cp0[nt], 4);
                cp0[nt] += __shfl_xor_sync(0xFFFFFFFF, cp0[nt], 8);
                cp0[nt] += __shfl_xor_sync(0xFFFFFFFF, cp0[nt], 16);
                cp1[nt] += __shfl_xor_sync(0xFFFFFFFF, cp1[nt], 4);
                cp1[nt] += __shfl_xor_sync(0xFFFFFFFF, cp1[nt], 8);
                cp1[nt] += __shfl_xor_sync(0xFFFFFFFF, cp1[nt], 16);
            }
            if ((lane & 3) == 0) {
#pragma unroll
                for (int mt = 0; mt < 2; mt++) {
                    int r = wy * 32 + mt * 16 + (lane >> 2);
                    red_row[r * 4 + wx] = rlo[mt];
                    red_row[(r + 8) * 4 + wx] = rhi[mt];
                }
            }
            if (lane < 4) {
#pragma unroll
                for (int nt = 0; nt < 4; nt++) {
                    int c = wx * 32 + nt * 8 + lane * 2;
                    red_col[c * 4 + wy] = cp0[nt];
                    red_col[(c + 1) * 4 + wy] = cp1[nt];
                }
            }
        }
        if (havenext) CP_WAIT0();
        __syncthreads();
        if (t > 0 && tid < 128) {
            float* red_row = (float*)(smem + RED_OFF + ((t - 1) & 1) * RED_PAR);
            float* red_col = red_row + 512;
            float rz = (red_row[tid * 4] + red_row[tid * 4 + 1]) +
                       (red_row[tid * 4 + 2] + red_row[tid * 4 + 3]);
            g_Zp[(size_t)(Ip * 128 + tid) * NT_ROW + Jp] = rz;
            if (!dtp) {
                float cz = (red_col[tid * 4] + red_col[tid * 4 + 1]) +
                           (red_col[tid * 4 + 2] + red_col[tid * 4 + 3]);
                g_Zp[(size_t)(Jp * 128 + tid) * NT_ROW + Ip] = cz;
            }
        }

#pragma unroll
        for (int mt = 0; mt < 2; mt++)
#pragma unroll
            for (int nt = 0; nt < 4; nt++)
#pragma unroll
                for (int q = 0; q < 4; q++) prev[mt][nt][q] = acc[mt][nt][q];
        Ip = I; Jp = J; dtp = (I == J);
        I = I1; J = J1; ap = apn;
    }

    // final epilogue for last tile
    {
        float rlo[2] = {0.f, 0.f}, rhi[2] = {0.f, 0.f};
        float cp0[4] = {0.f, 0.f, 0.f, 0.f}, cp1[4] = {0.f, 0.f, 0.f, 0.f};
#pragma unroll
        for (int ks = 0; ks < 8; ks++) {
            int mt = ks & 1, nt = ks >> 1;
            int lr = lrl0 + mt * 16;
            int lc = lcb0 + nt * 8;
            float v0 = (dtp && lc == lr)         ? EXP_DIAG : ex2f(prev[mt][nt][0] * EXP_SCALE);
            float v1 = (dtp && lc + 1 == lr)     ? EXP_DIAG : ex2f(prev[mt][nt][1] * EXP_SCALE);
            float v2 = (dtp && lc == lr + 8)     ? EXP_DIAG : ex2f(prev[mt][nt][2] * EXP_SCALE);
            float v3 = (dtp && lc + 1 == lr + 8) ? EXP_DIAG : ex2f(prev[mt][nt][3] * EXP_SCALE);
            rlo[mt] += v0 + v1;
            rhi[mt] += v2 + v3;
            cp0[nt] += v0 + v2;
            cp1[nt] += v1 + v3;
        }
        float* red_row = (float*)(smem + RED_OFF + ((cnt - 1) & 1) * RED_PAR);
        float* red_col = red_row + 512;
#pragma unroll
        for (int mt = 0; mt < 2; mt++) {
            rlo[mt] += __shfl_xor_sync(0xFFFFFFFF, rlo[mt], 1);
            rlo[mt] += __shfl_xor_sync(0xFFFFFFFF, rlo[mt], 2);
            rhi[mt] += __shfl_xor_sync(0xFFFFFFFF, rhi[mt], 1);
            rhi[mt] += __shfl_xor_sync(0xFFFFFFFF, rhi[mt], 2);
        }
#pragma unroll
        for (int nt = 0; nt < 4; nt++) {
            cp0[nt] += __shfl_xor_sync(0xFFFFFFFF, cp0[nt], 4);
            cp0[nt] += __shfl_xor_sync(0xFFFFFFFF, cp0[nt], 8);
            cp0[nt] += __shfl_xor_sync(0xFFFFFFFF, cp0[nt], 16);
            cp1[nt] += __shfl_xor_sync(0xFFFFFFFF, cp1[nt], 4);
            cp1[nt] += __shfl_xor_sync(0xFFFFFFFF, cp1[nt], 8);
            cp1[nt] += __shfl_xor_sync(0xFFFFFFFF, cp1[nt], 16);
        }
        if ((lane & 3) == 0) {
#pragma unroll
            for (int mt = 0; mt < 2; mt++) {
                int r = wy * 32 + mt * 16 + (lane >> 2);
                red_row[r * 4 + wx] = rlo[mt];
                red_row[(r + 8) * 4 + wx] = rhi[mt];
            }
        }
        if (lane < 4) {
#pragma unroll
            for (int nt = 0; nt < 4; nt++) {
                int c = wx * 32 + nt * 8 + lane * 2;
                red_col[c * 4 + wy] = cp0[nt];
                red_col[(c + 1) * 4 + wy] = cp1[nt];
            }
        }
        __syncthreads();
        if (tid < 128) {
            float rz = (red_row[tid * 4] + red_row[tid * 4 + 1]) +
                       (red_row[tid * 4 + 2] + red_row[tid * 4 + 3]);
            g_Zp[(size_t)(Ip * 128 + tid) * NT_ROW + Jp] = rz;
            if (!dtp) {
                float cz = (red_col[tid * 4] + red_col[tid * 4 + 1]) +
                           (red_col[tid * 4 + 2] + red_col[tid * 4 + 3]);
                g_Zp[(size_t)(Jp * 128 + tid) * NT_ROW + Ip] = cz;
            }
        }
    }
}

// ---------------- 3) contrastive + folded final reduction ----------------------------
__global__ void k_con(const int* __restrict__ tgt, float* __restrict__ out, int out_size) {
    int tid = threadIdx.x;
    int w = tid >> 5, lane = tid & 31;
    int row = blockIdx.x * 8 + w;
    int t = tgt[row];
    float zs = g_Zp[(size_t)row * NT_ROW + lane] + g_Zp[(size_t)row * NT_ROW + lane + 32];
    uint2 q = *(const uint2*)(g_embq + (size_t)row * 128 + lane * 4);
    const float4* sc = (const float4*)&g_clsum[t * DIM];
    float4 c0 = sc[lane * 2], c1 = sc[lane * 2 + 1];

    float2 e0 = e4m3x2_to_f2(q.x & 0xFFFFu);
    float2 e1 = e4m3x2_to_f2(q.x >> 16);
    float2 e2 = e4m3x2_to_f2(q.y & 0xFFFFu);
    float2 e3 = e4m3x2_to_f2(q.y >> 16);

    float dot = e0.x * c0.x + e0.y * c0.y + e1.x * c0.z + e1.y * c0.w +
                e2.x * c1.x + e2.y * c1.y + e3.x * c1.z + e3.y * c1.w;
#pragma unroll
    for (int off = 16; off > 0; off >>= 1) {
        dot += __shfl_xor_sync(0xFFFFFFFF, dot, off);
        zs += __shfl_xor_sync(0xFFFFFFFF, zs, off);
    }
    if (lane == 0) {
        float logZ = logf(zs + 1e-8f);
        float npos = g_clcnt[t] - 1.0f;
        float msum = (dot - 1.0f) * INV_T;
        g_con[row] = (npos * logZ - msum) / fmaxf(npos, 1.0f);
    }

    // ---- folded final: last of 1024 blocks reduces everything ----
    __syncthreads();
    __shared__ unsigned s_last;
    if (tid == 0) {
        __threadfence();
        unsigned old = atomicAdd(&g_fin_cnt, 1u);
        s_last = ((old & 1023u) == 1023u) ? 1u : 0u;
    }
    __syncthreads();
    if (s_last) {
        __shared__ float s[256];
        float cs = 0.f;
        for (int i = tid; i < N; i += 256) cs += g_con[i];
        s[tid] = cs;
        __syncthreads();
        for (int off = 128; off > 0; off >>= 1) {
            if (tid < off) s[tid] += s[tid + off];
            __syncthreads();
        }
        __shared__ float con_sum;
        if (tid == 0) con_sum = s[0];
        __syncthreads();

        s[tid] = g_ce_part[tid];
        __syncthreads();
        for (int off = 128; off > 0; off >>= 1) {
            if (tid < off) s[tid] += s[tid + off];
            __syncthreads();
        }
        if (tid == 0) {
            float ce_mean = s[0] * (1.0f / N);
            float con_mean = con_sum * (1.0f / N);
            out[0] = ce_mean + ALPHA * con_mean;
            if (out_size > 1) out[1] = ce_mean;
            if (out_size > 2) out[2] = con_mean;
        }
    }
}

// ---------------- launcher ----------------------------------------------------------
extern "C" void kernel_launch(void* const* d_in, const int* in_sizes, int n_in,
                              void* d_out, int out_size) {
    const float* logits = (const float*)d_in[0];
    const float* emb = (const float*)d_in[1];
    const int* tgt = (const int*)d_in[2];
    float* out = (float*)d_out;

    cudaFuncSetAttribute(k_sim_sym, cudaFuncAttributeMaxDynamicSharedMemorySize, SMEM_TOTAL);

    k_norm<<<N / 8, 256>>>(emb);
    k_sim_sym<<<148, 512, SMEM_TOTAL>>>(logits, tgt);
    k_con<<<N / 8, 256>>>(tgt, out, out_size);
}

// round 16
// speedup vs baseline: 1.0675x; 1.0675x over previous
#include <cuda_runtime.h>
#include <cuda_fp16.h>
#include <math.h>
#include <stdint.h>

#define N 8192
#define CLS 8
#define DIM 256
#define INV_T 14.285714285714286f
#define EXP_SCALE 20.60992915555662f   /* (1/0.07) * log2(e) */
#define ALPHA 0.3f
#define LSM 0.1f
#define NT_ROW 64
#define NCHUNK 128
#define NORM_WARPS (148 * 16)

// ---------------- scratch ------------------------------------------------------------
__device__ float g_embn[N * DIM];
__device__ uint16_t g_embq[N * DIM / 2];
__device__ float g_clsum_part[NCHUNK * CLS * DIM];
__device__ float g_clcnt_part[NCHUNK * CLS];
__device__ float g_clsum[CLS * DIM];
__device__ float g_clcnt[CLS];
__device__ float g_Zp[N * NT_ROW];
__device__ float g_con[N];
__device__ float g_ce_part[16 * 16];

// ---------------- helpers ------------------------------------------------------------
__device__ __forceinline__ uint32_t smem_u32(const void* p) {
    uint32_t a;
    asm("{ .reg .u64 t; cvta.to.shared.u64 t, %1; cvt.u32.u64 %0, t; }" : "=r"(a) : "l"(p));
    return a;
}
__device__ __forceinline__ float ex2f(float x) {
    float y; asm("ex2.approx.f32 %0, %1;" : "=f"(y) : "f"(x)); return y;
}
__device__ __forceinline__ void cp16(uint32_t dst, const void* src) {
    asm volatile("cp.async.cg.shared.global [%0], [%1], 16;" :: "r"(dst), "l"(src));
}
#define CP_COMMIT() asm volatile("cp.async.commit_group;" ::: "memory")
#define CP_WAIT0()  asm volatile("cp.async.wait_group 0;" ::: "memory")

__device__ __forceinline__ void ldsm4(uint32_t& r0, uint32_t& r1, uint32_t& r2, uint32_t& r3,
                                      uint32_t addr) {
    asm volatile("ldmatrix.sync.aligned.m8n8.x4.shared.b16 {%0,%1,%2,%3}, [%4];"
                 : "=r"(r0), "=r"(r1), "=r"(r2), "=r"(r3) : "r"(addr));
}
__device__ __forceinline__ void mma_fp8(float* c, uint32_t a0, uint32_t a1, uint32_t a2,
                                        uint32_t a3, uint32_t b0, uint32_t b1) {
    asm volatile("mma.sync.aligned.m16n8k32.row.col.f32.e4m3.e4m3.f32 "
                 "{%0,%1,%2,%3}, {%4,%5,%6,%7}, {%8,%9}, {%0,%1,%2,%3};"
                 : "+f"(c[0]), "+f"(c[1]), "+f"(c[2]), "+f"(c[3])
                 : "r"(a0), "r"(a1), "r"(a2), "r"(a3), "r"(b0), "r"(b1));
}
__device__ __forceinline__ uint16_t f2e4m3x2(float hi, float lo) {
    uint16_t r;
    asm("cvt.rn.satfinite.e4m3x2.f32 %0, %1, %2;" : "=h"(r) : "f"(hi), "f"(lo));
    return r;
}
__device__ __forceinline__ float2 e4m3x2_to_f2(uint32_t p) {
    uint32_t h;
    float lo, hi;
    asm("cvt.rn.f16x2.e4m3x2 %0, %1;" : "=r"(h) : "h"((uint16_t)p));
    asm("{ .reg .f16 a, b; mov.b32 {a, b}, %2; cvt.f32.f16 %0, a; cvt.f32.f16 %1, b; }"
        : "=f"(lo), "=f"(hi) : "r"(h));
    return make_float2(lo, hi);
}

// ---------------- 1) normalize + fp8 convert: one wave, pipelined rows ---------------
__global__ void __launch_bounds__(512) k_norm(const float* __restrict__ emb) {
    int wid = threadIdx.x >> 5, lane = threadIdx.x & 31;
    int gw = blockIdx.x * 16 + wid;

    int row = gw;
    if (row >= N) return;
    const float4* src = (const float4*)(emb + (size_t)row * DIM);
    float4 a = src[lane * 2], b = src[lane * 2 + 1];

    while (row < N) {
        int nrow = row + NORM_WARPS;
        float4 na, nb;
        if (nrow < N) {                 // prefetch next row before current reduction
            const float4* nsrc = (const float4*)(emb + (size_t)nrow * DIM);
            na = nsrc[lane * 2];
            nb = nsrc[lane * 2 + 1];
        }
        float ss = a.x * a.x + a.y * a.y + a.z * a.z + a.w * a.w +
                   b.x * b.x + b.y * b.y + b.z * b.z + b.w * b.w;
#pragma unroll
        for (int off = 16; off > 0; off >>= 1) ss += __shfl_xor_sync(0xFFFFFFFF, ss, off);
        float inv = 1.0f / fmaxf(sqrtf(ss), 1e-12f);
        a.x *= inv; a.y *= inv; a.z *= inv; a.w *= inv;
        b.x *= inv; b.y *= inv; b.z *= inv; b.w *= inv;
        float4* dst = (float4*)(g_embn + (size_t)row * DIM);
        dst[lane * 2] = a;
        dst[lane * 2 + 1] = b;
        uint32_t u0 = (uint32_t)f2e4m3x2(a.y, a.x) | ((uint32_t)f2e4m3x2(a.w, a.z) << 16);
        uint32_t u1 = (uint32_t)f2e4m3x2(b.y, b.x) | ((uint32_t)f2e4m3x2(b.w, b.z) << 16);
        *(uint2*)(g_embq + (size_t)row * 128 + lane * 4) = make_uint2(u0, u1);
        a = na; b = nb;
        row = nrow;
    }
}

// ---------------- 2) HOT: symmetric Z + folded side jobs (identical to R14) ----------
#define SAB 272
#define A_BYTES (128 * SAB)
#define AS(p) ((p) * A_BYTES)
#define BS(b) ((2 + (b)) * A_BYTES)
#define RED_OFF (4 * A_BYTES)
#define RED_PAR 4096
#define SMEM_TOTAL (RED_OFF + 2 * RED_PAR)

__device__ __forceinline__ void load_tile_async(uint32_t sbase, int grow0, int tid) {
    const char* src = (const char*)g_embq + (size_t)grow0 * 256;
#pragma unroll
    for (int i = 0; i < 4; i++) {
        int idx = tid + i * 512;
        int row = idx >> 4, cb = idx & 15;
        cp16(sbase + row * SAB + cb * 16, src + (size_t)row * 256 + cb * 16);
    }
}

__global__ void __launch_bounds__(512, 1) k_sim_sym(const float* __restrict__ logits,
                                                   const int* __restrict__ tgt) {
    extern __shared__ char smem[];
    uint32_t sb = smem_u32(smem);
    int tid = threadIdx.x;
    int lane = tid & 31;
    int wid = tid >> 5;
    int wx = wid & 3;
    int wy = wid >> 2;
    int bid = blockIdx.x;

    int base = bid * 14 + (bid < 8 ? bid : 8);
    int cnt = 14 + (bid < 8 ? 1 : 0);

    int idx = base, I = 0;
    while (idx >= NT_ROW - I) { idx -= NT_ROW - I; I++; }
    int J = I + idx;

    int ap = 0;
    load_tile_async(sb + AS(0), I * 128, tid);
    if (J != I) load_tile_async(sb + BS(0), J * 128, tid);
    CP_COMMIT();

    if (bid >= 8 && bid < 72) {
        int half = tid >> 8;
        int d = tid & 255;
        int chunk = (bid - 8) * 2 + half;
        int i0 = chunk * 64;
        float a[CLS];
#pragma unroll
        for (int c = 0; c < CLS; c++) a[c] = 0.f;
        for (int k = 0; k < 64; k++) {
            int tg = tgt[i0 + k];
            float v = g_embn[(size_t)(i0 + k) * DIM + d];
#pragma unroll
            for (int c = 0; c < CLS; c++) a[c] += (tg == c) ? v : 0.f;
        }
#pragma unroll
        for (int c = 0; c < CLS; c++) g_clsum_part[(chunk * CLS + c) * DIM + d] = a[c];
        if (d == 0) {
            int cc[CLS];
#pragma unroll
            for (int c = 0; c < CLS; c++) cc[c] = 0;
            for (int k = 0; k < 64; k++) {
                int tg = tgt[i0 + k];
#pragma unroll
                for (int c = 0; c < CLS; c++) cc[c] += (tg == c);
            }
#pragma unroll
            for (int c = 0; c < CLS; c++) g_clcnt_part[chunk * CLS + c] = (float)cc[c];
        }
    } else if (bid >= 72 && bid < 88) {
        int chunk = bid - 72;
        int i = chunk * 512 + tid;
        const float4* p = (const float4*)(logits + (size_t)i * CLS);
        float4 u = p[0], w = p[1];
        float x[CLS] = {u.x, u.y, u.z, u.w, w.x, w.y, w.z, w.w};
        float m = x[0];
#pragma unroll
        for (int j = 1; j < CLS; j++) m = fmaxf(m, x[j]);
        float se = 0.f;
#pragma unroll
        for (int j = 0; j < CLS; j++) se += expf(x[j] - m);
        float lse = m + logf(se);
        int tg = tgt[i];
        float nll = lse - x[tg];
        float sx = 0.f;
#pragma unroll
        for (int j = 0; j < CLS; j++) sx += x[j];
        float smooth = lse - sx * (1.0f / CLS);
        float ce = (1.0f - LSM) * nll + LSM * smooth;
        float pt = expf(-ce);
        float omp = 1.0f - pt;
        float focal = omp * omp * ce;
#pragma unroll
        for (int off = 16; off > 0; off >>= 1)
            focal += __shfl_xor_sync(0xFFFFFFFF, focal, off);
        if (lane == 0) g_ce_part[chunk * 16 + wid] = focal;
    }

    CP_WAIT0();
    __syncthreads();

    uint32_t a_lane = (wy * 32 + (lane & 15)) * SAB + ((lane >> 4) << 4);
    uint32_t b_lane = ((lane & 7) + ((lane >> 4) << 3)) * SAB + (((lane >> 3) & 1) << 4) +
                      (wx * 32) * SAB;

    const float EXP_DIAG = expf(INV_T);
    int lrl0 = wy * 32 + (lane >> 2);
    int lcb0 = wx * 32 + (lane & 3) * 2;

    float prev[2][4][4];
    int Ip = 0, Jp = 0;
    bool dtp = false;

    for (int t = 0; t < cnt; t++) {
        int I1 = I, J1 = J + 1;
        if (J1 == NT_ROW) { I1 = I + 1; J1 = I1; }
        bool havenext = (t + 1 < cnt);
        int apn = ap;
        if (havenext) {
            if (I1 != I) {
                apn = ap ^ 1;
                load_tile_async(sb + AS(apn), I1 * 128, tid);
            }
            if (J1 != I1) {
                load_tile_async(sb + BS((t + 1) & 1), J1 * 128, tid);
            }
            CP_COMMIT();
        }

        bool dt = (I == J);
        uint32_t a_addr = sb + AS(ap) + a_lane;
        uint32_t bbuf = (dt ? (sb + AS(ap)) : (sb + BS(t & 1))) + b_lane;

        float acc[2][4][4];
#pragma unroll
        for (int mt = 0; mt < 2; mt++)
#pragma unroll
            for (int nt = 0; nt < 4; nt++)
#pragma unroll
                for (int q = 0; q < 4; q++) acc[mt][nt][q] = 0.f;

        float rlo[2] = {0.f, 0.f}, rhi[2] = {0.f, 0.f};
        float cp0[4] = {0.f, 0.f, 0.f, 0.f}, cp1[4] = {0.f, 0.f, 0.f, 0.f};

#pragma unroll
        for (int ks = 0; ks < 8; ks++) {
            uint32_t koff = ks * 32;
            uint32_t a0[4], a1[4];
            ldsm4(a0[0], a0[1], a0[2], a0[3], a_addr + koff);
            ldsm4(a1[0], a1[1], a1[2], a1[3], a_addr + 16 * SAB + koff);
            uint32_t bfr[2][4];
#pragma unroll
            for (int p = 0; p < 2; p++)
                ldsm4(bfr[p][0], bfr[p][1], bfr[p][2], bfr[p][3],
                      bbuf + (p * 16) * SAB + koff);
#pragma unroll
            for (int nt = 0; nt < 4; nt++) {
                uint32_t bb0 = bfr[nt >> 1][(nt & 1) * 2];
                uint32_t bb1 = bfr[nt >> 1][(nt & 1) * 2 + 1];
                mma_fp8(acc[0][nt], a0[0], a0[1], a0[2], a0[3], bb0, bb1);
                mma_fp8(acc[1][nt], a1[0], a1[1], a1[2], a1[3], bb0, bb1);
            }
            if (t > 0) {
                int mt = ks & 1, nt = ks >> 1;
                int lr = lrl0 + mt * 16;
                int lc = lcb0 + nt * 8;
                float v0 = (dtp && lc == lr)         ? EXP_DIAG : ex2f(prev[mt][nt][0] * EXP_SCALE);
                float v1 = (dtp && lc + 1 == lr)     ? EXP_DIAG : ex2f(prev[mt][nt][1] * EXP_SCALE);
                float v2 = (dtp && lc == lr + 8)     ? EXP_DIAG : ex2f(prev[mt][nt][2] * EXP_SCALE);
                float v3 = (dtp && lc + 1 == lr + 8) ? EXP_DIAG : ex2f(prev[mt][nt][3] * EXP_SCALE);
                rlo[mt] += v0 + v1;
                rhi[mt] += v2 + v3;
                cp0[nt] += v0 + v2;
                cp1[nt] += v1 + v3;
            }
        }

        if (t > 0) {
            float* red_row = (float*)(smem + RED_OFF + ((t - 1) & 1) * RED_PAR);
            float* red_col = red_row + 512;
#pragma unroll
            for (int mt = 0; mt < 2; mt++) {
                rlo[mt] += __shfl_xor_sync(0xFFFFFFFF, rlo[mt], 1);
                rlo[mt] += __shfl_xor_sync(0xFFFFFFFF, rlo[mt], 2);
                rhi[mt] += __shfl_xor_sync(0xFFFFFFFF, rhi[mt], 1);
                rhi[mt] += __shfl_xor_sync(0xFFFFFFFF, rhi[mt], 2);
            }
#pragma unroll
            for (int nt = 0; nt < 4; nt++) {
                cp0[nt] += __shfl_xor_sync(0xFFFFFFFF, cp0[nt], 4);
                cp0[nt] += __shfl_xor_sync(0xFFFFFFFF, cp0[nt], 8);
                cp0[nt] += __shfl_xor_sync(0xFFFFFFFF, cp0[nt], 16);
                cp1[nt] += __shfl_xor_sync(0xFFFFFFFF, cp1[nt], 4);
                cp1[nt] += __shfl_xor_sync(0xFFFFFFFF, cp1[nt], 8);
                cp1[nt] += __shfl_xor_sync(0xFFFFFFFF, cp1[nt], 16);
            }
            if ((lane & 3) == 0) {
#pragma unroll
                for (int mt = 0; mt < 2; mt++) {
                    int r = wy * 32 + mt * 16 + (lane >> 2);
                    red_row[r * 4 + wx] = rlo[mt];
                    red_row[(r + 8) * 4 + wx] = rhi[mt];
                }
            }
            if (lane < 4) {
#pragma unroll
                for (int nt = 0; nt < 4; nt++) {
                    int c = wx * 32 + nt * 8 + lane * 2;
                    red_col[c * 4 + wy] = cp0[nt];
                    red_col[(c + 1) * 4 + wy] = cp1[nt];
                }
            }
        }
        if (havenext) CP_WAIT0();
        __syncthreads();
        if (t > 0 && tid < 128) {
            float* red_row = (float*)(smem + RED_OFF + ((t - 1) & 1) * RED_PAR);
            float* red_col = red_row + 512;
            float rz = (red_row[tid * 4] + red_row[tid * 4 + 1]) +
                       (red_row[tid * 4 + 2] + red_row[tid * 4 + 3]);
            g_Zp[(size_t)(Ip * 128 + tid) * NT_ROW + Jp] = rz;
            if (!dtp) {
                float cz = (red_col[tid * 4] + red_col[tid * 4 + 1]) +
                           (red_col[tid * 4 + 2] + red_col[tid * 4 + 3]);
                g_Zp[(size_t)(Jp * 128 + tid) * NT_ROW + Ip] = cz;
            }
        }

#pragma unroll
        for (int mt = 0; mt < 2; mt++)
#pragma unroll
            for (int nt = 0; nt < 4; nt++)
#pragma unroll
                for (int q = 0; q < 4; q++) prev[mt][nt][q] = acc[mt][nt][q];
        Ip = I; Jp = J; dtp = (I == J);
        I = I1; J = J1; ap = apn;
    }

    // final epilogue for last tile
    {
        float rlo[2] = {0.f, 0.f}, rhi[2] = {0.f, 0.f};
        float cp0[4] = {0.f, 0.f, 0.f, 0.f}, cp1[4] = {0.f, 0.f, 0.f, 0.f};
#pragma unroll
        for (int ks = 0; ks < 8; ks++) {
            int mt = ks & 1, nt = ks >> 1;
            int lr = lrl0 + mt * 16;
            int lc = lcb0 + nt * 8;
            float v0 = (dtp && lc == lr)         ? EXP_DIAG : ex2f(prev[mt][nt][0] * EXP_SCALE);
            float v1 = (dtp && lc + 1 == lr)     ? EXP_DIAG : ex2f(prev[mt][nt][1] * EXP_SCALE);
            float v2 = (dtp && lc == lr + 8)     ? EXP_DIAG : ex2f(prev[mt][nt][2] * EXP_SCALE);
            float v3 = (dtp && lc + 1 == lr + 8) ? EXP_DIAG : ex2f(prev[mt][nt][3] * EXP_SCALE);
            rlo[mt] += v0 + v1;
            rhi[mt] += v2 + v3;
            cp0[nt] += v0 + v2;
            cp1[nt] += v1 + v3;
        }
        float* red_row = (float*)(smem + RED_OFF + ((cnt - 1) & 1) * RED_PAR);
        float* red_col = red_row + 512;
#pragma unroll
        for (int mt = 0; mt < 2; mt++) {
            rlo[mt] += __shfl_xor_sync(0xFFFFFFFF, rlo[mt], 1);
            rlo[mt] += __shfl_xor_sync(0xFFFFFFFF, rlo[mt], 2);
            rhi[mt] += __shfl_xor_sync(0xFFFFFFFF, rhi[mt], 1);
            rhi[mt] += __shfl_xor_sync(0xFFFFFFFF, rhi[mt], 2);
        }
#pragma unroll
        for (int nt = 0; nt < 4; nt++) {
            cp0[nt] += __shfl_xor_sync(0xFFFFFFFF, cp0[nt], 4);
            cp0[nt] += __shfl_xor_sync(0xFFFFFFFF, cp0[nt], 8);
            cp0[nt] += __shfl_xor_sync(0xFFFFFFFF, cp0[nt], 16);
            cp1[nt] += __shfl_xor_sync(0xFFFFFFFF, cp1[nt], 4);
            cp1[nt] += __shfl_xor_sync(0xFFFFFFFF, cp1[nt], 8);
            cp1[nt] += __shfl_xor_sync(0xFFFFFFFF, cp1[nt], 16);
        }
        if ((lane & 3) == 0) {
#pragma unroll
            for (int mt = 0; mt < 2; mt++) {
                int r = wy * 32 + mt * 16 + (lane >> 2);
                red_row[r * 4 + wx] = rlo[mt];
                red_row[(r + 8) * 4 + wx] = rhi[mt];
            }
        }
        if (lane < 4) {
#pragma unroll
            for (int nt = 0; nt < 4; nt++) {
                int c = wx * 32 + nt * 8 + lane * 2;
                red_col[c * 4 + wy] = cp0[nt];
                red_col[(c + 1) * 4 + wy] = cp1[nt];
            }
        }
        __syncthreads();
        if (tid < 128) {
            float rz = (red_row[tid * 4] + red_row[tid * 4 + 1]) +
                       (red_row[tid * 4 + 2] + red_row[tid * 4 + 3]);
            g_Zp[(size_t)(Ip * 128 + tid) * NT_ROW + Jp] = rz;
            if (!dtp) {
                float cz = (red_col[tid * 4] + red_col[tid * 4 + 1]) +
                           (red_col[tid * 4 + 2] + red_col[tid * 4 + 3]);
                g_Zp[(size_t)(Jp * 128 + tid) * NT_ROW + Ip] = cz;
            }
        }
    }
}

// ---------------- 3) class-sum finalize ----------------------------------------------
__global__ void k_clsfinal() {
    int c = blockIdx.x, d = threadIdx.x;
    float s = 0.f;
    for (int b = 0; b < NCHUNK; b++) s += g_clsum_part[(b * CLS + c) * DIM + d];
    g_clsum[c * DIM + d] = s;
    if (d == 0) {
        float cn = 0.f;
        for (int b = 0; b < NCHUNK; b++) cn += g_clcnt_part[b * CLS + c];
        g_clcnt[c] = cn;
    }
}

// ---------------- 4) per-row contrastive: fp8 embedding reads (R14 proven) -----------
__global__ void k_con(const int* __restrict__ tgt) {
    int w = threadIdx.x >> 5, lane = threadIdx.x & 31;
    int row = blockIdx.x * 8 + w;
    int t = tgt[row];
    float zs = g_Zp[(size_t)row * NT_ROW + lane] + g_Zp[(size_t)row * NT_ROW + lane + 32];
    uint2 q = *(const uint2*)(g_embq + (size_t)row * 128 + lane * 4);
    const float4* sc = (const float4*)&g_clsum[t * DIM];
    float4 c0 = sc[lane * 2], c1 = sc[lane * 2 + 1];

    float2 e0 = e4m3x2_to_f2(q.x & 0xFFFFu);
    float2 e1 = e4m3x2_to_f2(q.x >> 16);
    float2 e2 = e4m3x2_to_f2(q.y & 0xFFFFu);
    float2 e3 = e4m3x2_to_f2(q.y >> 16);

    float dot = e0.x * c0.x + e0.y * c0.y + e1.x * c0.z + e1.y * c0.w +
                e2.x * c1.x + e2.y * c1.y + e3.x * c1.z + e3.y * c1.w;
#pragma unroll
    for (int off = 16; off > 0; off >>= 1) {
        dot += __shfl_xor_sync(0xFFFFFFFF, dot, off);
        zs += __shfl_xor_sync(0xFFFFFFFF, zs, off);
    }
    if (lane == 0) {
        float logZ = logf(zs + 1e-8f);
        float npos = g_clcnt[t] - 1.0f;
        float msum = (dot - 1.0f) * INV_T;
        g_con[row] = (npos * logZ - msum) / fmaxf(npos, 1.0f);
    }
}

// ---------------- 5) final reduction -------------------------------------------------
__global__ void k_final(float* __restrict__ out, int out_size) {
    __shared__ float s[256];
    int t = threadIdx.x;

    float cs = 0.f;
    for (int i = t; i < N; i += 256) cs += g_con[i];
    s[t] = cs;
    __syncthreads();
    for (int off = 128; off > 0; off >>= 1) {
        if (t < off) s[t] += s[t + off];
        __syncthreads();
    }
    __shared__ float con_sum;
    if (t == 0) con_sum = s[0];
    __syncthreads();

    s[t] = g_ce_part[t];
    __syncthreads();
    for (int off = 128; off > 0; off >>= 1) {
        if (t < off) s[t] += s[t + off];
        __syncthreads();
    }
    if (t == 0) {
        float ce_mean = s[0] * (1.0f / N);
        float con_mean = con_sum * (1.0f / N);
        out[0] = ce_mean + ALPHA * con_mean;
        if (out_size > 1) out[1] = ce_mean;
        if (out_size > 2) out[2] = con_mean;
    }
}

// ---------------- launcher ----------------------------------------------------------
extern "C" void kernel_launch(void* const* d_in, const int* in_sizes, int n_in,
                              void* d_out, int out_size) {
    const float* logits = (const float*)d_in[0];
    const float* emb = (const float*)d_in[1];
    const int* tgt = (const int*)d_in[2];
    float* out = (float*)d_out;

    cudaFuncSetAttribute(k_sim_sym, cudaFuncAttributeMaxDynamicSharedMemorySize, SMEM_TOTAL);

    k_norm<<<148, 512>>>(emb);
    k_sim_sym<<<148, 512, SMEM_TOTAL>>>(logits, tgt);
    k_clsfinal<<<CLS, DIM>>>();
    k_con<<<N / 8, 256>>>(tgt);
    k_final<<<1, 256>>>(out, out_size);
}

// round 17
// speedup vs baseline: 1.0907x; 1.0217x over previous
#include <cuda_runtime.h>
#include <cuda_fp16.h>
#include <math.h>
#include <stdint.h>

#define N 8192
#define CLS 8
#define DIM 256
#define INV_T 14.285714285714286f
#define EXP_SCALE 20.60992915555662f   /* (1/0.07) * log2(e) */
#define ALPHA 0.3f
#define LSM 0.1f
#define NT_ROW 64
#define NCHUNK 128
#define NORM_WARPS (148 * 16)

// ---------------- scratch ------------------------------------------------------------
__device__ float g_embn[N * DIM];
__device__ uint16_t g_embq[N * DIM / 2];
__device__ float g_clsum_part[NCHUNK * CLS * DIM];
__device__ float g_clcnt_part[NCHUNK * CLS];
__device__ float g_clsum[CLS * DIM];
__device__ float g_clcnt[CLS];
__device__ float g_Zp[N * NT_ROW];
__device__ float g_con[N];
__device__ float g_ce_part[16 * 16];

// ---------------- helpers ------------------------------------------------------------
__device__ __forceinline__ uint32_t smem_u32(const void* p) {
    uint32_t a;
    asm("{ .reg .u64 t; cvta.to.shared.u64 t, %1; cvt.u32.u64 %0, t; }" : "=r"(a) : "l"(p));
    return a;
}
__device__ __forceinline__ float ex2f(float x) {
    float y; asm("ex2.approx.f32 %0, %1;" : "=f"(y) : "f"(x)); return y;
}
__device__ __forceinline__ void cp16(uint32_t dst, const void* src) {
    asm volatile("cp.async.cg.shared.global [%0], [%1], 16;" :: "r"(dst), "l"(src));
}
#define CP_COMMIT() asm volatile("cp.async.commit_group;" ::: "memory")
#define CP_WAIT0()  asm volatile("cp.async.wait_group 0;" ::: "memory")

__device__ __forceinline__ void ldsm4(uint32_t& r0, uint32_t& r1, uint32_t& r2, uint32_t& r3,
                                      uint32_t addr) {
    asm volatile("ldmatrix.sync.aligned.m8n8.x4.shared.b16 {%0,%1,%2,%3}, [%4];"
                 : "=r"(r0), "=r"(r1), "=r"(r2), "=r"(r3) : "r"(addr));
}
__device__ __forceinline__ void mma_fp8(float* c, uint32_t a0, uint32_t a1, uint32_t a2,
                                        uint32_t a3, uint32_t b0, uint32_t b1) {
    asm volatile("mma.sync.aligned.m16n8k32.row.col.f32.e4m3.e4m3.f32 "
                 "{%0,%1,%2,%3}, {%4,%5,%6,%7}, {%8,%9}, {%0,%1,%2,%3};"
                 : "+f"(c[0]), "+f"(c[1]), "+f"(c[2]), "+f"(c[3])
                 : "r"(a0), "r"(a1), "r"(a2), "r"(a3), "r"(b0), "r"(b1));
}
__device__ __forceinline__ uint16_t f2e4m3x2(float hi, float lo) {
    uint16_t r;
    asm("cvt.rn.satfinite.e4m3x2.f32 %0, %1, %2;" : "=h"(r) : "f"(hi), "f"(lo));
    return r;
}
__device__ __forceinline__ float2 e4m3x2_to_f2(uint32_t p) {
    uint32_t h;
    float lo, hi;
    asm("cvt.rn.f16x2.e4m3x2 %0, %1;" : "=r"(h) : "h"((uint16_t)p));
    asm("{ .reg .f16 a, b; mov.b32 {a, b}, %2; cvt.f32.f16 %0, a; cvt.f32.f16 %1, b; }"
        : "=f"(lo), "=f"(hi) : "r"(h));
    return make_float2(lo, hi);
}

// ---------------- 1) normalize + fp8 convert: one wave, pipelined rows ---------------
__global__ void __launch_bounds__(512) k_norm(const float* __restrict__ emb) {
    int wid = threadIdx.x >> 5, lane = threadIdx.x & 31;
    int row = blockIdx.x * 16 + wid;
    if (row >= N) return;
    const float4* src = (const float4*)(emb + (size_t)row * DIM);
    float4 a = src[lane * 2], b = src[lane * 2 + 1];

    while (row < N) {
        int nrow = row + NORM_WARPS;
        float4 na, nb;
        if (nrow < N) {
            const float4* nsrc = (const float4*)(emb + (size_t)nrow * DIM);
            na = nsrc[lane * 2];
            nb = nsrc[lane * 2 + 1];
        }
        float ss = a.x * a.x + a.y * a.y + a.z * a.z + a.w * a.w +
                   b.x * b.x + b.y * b.y + b.z * b.z + b.w * b.w;
#pragma unroll
        for (int off = 16; off > 0; off >>= 1) ss += __shfl_xor_sync(0xFFFFFFFF, ss, off);
        float inv = 1.0f / fmaxf(sqrtf(ss), 1e-12f);
        a.x *= inv; a.y *= inv; a.z *= inv; a.w *= inv;
        b.x *= inv; b.y *= inv; b.z *= inv; b.w *= inv;
        float4* dst = (float4*)(g_embn + (size_t)row * DIM);
        dst[lane * 2] = a;
        dst[lane * 2 + 1] = b;
        uint32_t u0 = (uint32_t)f2e4m3x2(a.y, a.x) | ((uint32_t)f2e4m3x2(a.w, a.z) << 16);
        uint32_t u1 = (uint32_t)f2e4m3x2(b.y, b.x) | ((uint32_t)f2e4m3x2(b.w, b.z) << 16);
        *(uint2*)(g_embq + (size_t)row * 128 + lane * 4) = make_uint2(u0, u1);
        a = na; b = nb;
        row = nrow;
    }
}

// ---------------- 2) HOT: symmetric Z + side jobs + end-slack clsfinal ---------------
#define SAB 272
#define A_BYTES (128 * SAB)
#define AS(p) ((p) * A_BYTES)
#define BS(b) ((2 + (b)) * A_BYTES)
#define RED_OFF (4 * A_BYTES)
#define RED_PAR 4096
#define SMEM_TOTAL (RED_OFF + 2 * RED_PAR)

__device__ __forceinline__ void load_tile_async(uint32_t sbase, int grow0, int tid) {
    const char* src = (const char*)g_embq + (size_t)grow0 * 256;
#pragma unroll
    for (int i = 0; i < 4; i++) {
        int idx = tid + i * 512;
        int row = idx >> 4, cb = idx & 15;
        cp16(sbase + row * SAB + cb * 16, src + (size_t)row * 256 + cb * 16);
    }
}

__global__ void __launch_bounds__(512, 1) k_sim_sym(const float* __restrict__ logits,
                                                   const int* __restrict__ tgt) {
    extern __shared__ char smem[];
    uint32_t sb = smem_u32(smem);
    int tid = threadIdx.x;
    int lane = tid & 31;
    int wid = tid >> 5;
    int wx = wid & 3;
    int wy = wid >> 2;
    int bid = blockIdx.x;

    int base = bid * 14 + (bid < 8 ? bid : 8);
    int cnt = 14 + (bid < 8 ? 1 : 0);

    int idx = base, I = 0;
    while (idx >= NT_ROW - I) { idx -= NT_ROW - I; I++; }
    int J = I + idx;

    int ap = 0;
    load_tile_async(sb + AS(0), I * 128, tid);
    if (J != I) load_tile_async(sb + BS(0), J * 128, tid);
    CP_COMMIT();

    if (bid >= 8 && bid < 72) {
        int half = tid >> 8;
        int d = tid & 255;
        int chunk = (bid - 8) * 2 + half;
        int i0 = chunk * 64;
        float a[CLS];
#pragma unroll
        for (int c = 0; c < CLS; c++) a[c] = 0.f;
        for (int k = 0; k < 64; k++) {
            int tg = tgt[i0 + k];
            float v = g_embn[(size_t)(i0 + k) * DIM + d];
#pragma unroll
            for (int c = 0; c < CLS; c++) a[c] += (tg == c) ? v : 0.f;
        }
#pragma unroll
        for (int c = 0; c < CLS; c++) g_clsum_part[(chunk * CLS + c) * DIM + d] = a[c];
        if (d == 0) {
            int cc[CLS];
#pragma unroll
            for (int c = 0; c < CLS; c++) cc[c] = 0;
            for (int k = 0; k < 64; k++) {
                int tg = tgt[i0 + k];
#pragma unroll
                for (int c = 0; c < CLS; c++) cc[c] += (tg == c);
            }
#pragma unroll
            for (int c = 0; c < CLS; c++) g_clcnt_part[chunk * CLS + c] = (float)cc[c];
        }
        __threadfence();   // publish partials to L2 before tile work (off critical path)
    } else if (bid >= 72 && bid < 88) {
        int chunk = bid - 72;
        int i = chunk * 512 + tid;
        const float4* p = (const float4*)(logits + (size_t)i * CLS);
        float4 u = p[0], w = p[1];
        float x[CLS] = {u.x, u.y, u.z, u.w, w.x, w.y, w.z, w.w};
        float m = x[0];
#pragma unroll
        for (int j = 1; j < CLS; j++) m = fmaxf(m, x[j]);
        float se = 0.f;
#pragma unroll
        for (int j = 0; j < CLS; j++) se += expf(x[j] - m);
        float lse = m + logf(se);
        int tg = tgt[i];
        float nll = lse - x[tg];
        float sx = 0.f;
#pragma unroll
        for (int j = 0; j < CLS; j++) sx += x[j];
        float smooth = lse - sx * (1.0f / CLS);
        float ce = (1.0f - LSM) * nll + LSM * smooth;
        float pt = expf(-ce);
        float omp = 1.0f - pt;
        float focal = omp * omp * ce;
#pragma unroll
        for (int off = 16; off > 0; off >>= 1)
            focal += __shfl_xor_sync(0xFFFFFFFF, focal, off);
        if (lane == 0) g_ce_part[chunk * 16 + wid] = focal;
    }

    CP_WAIT0();
    __syncthreads();

    uint32_t a_lane = (wy * 32 + (lane & 15)) * SAB + ((lane >> 4) << 4);
    uint32_t b_lane = ((lane & 7) + ((lane >> 4) << 3)) * SAB + (((lane >> 3) & 1) << 4) +
                      (wx * 32) * SAB;

    const float EXP_DIAG = expf(INV_T);
    int lrl0 = wy * 32 + (lane >> 2);
    int lcb0 = wx * 32 + (lane & 3) * 2;

    float prev[2][4][4];
    int Ip = 0, Jp = 0;
    bool dtp = false;

    for (int t = 0; t < cnt; t++) {
        int I1 = I, J1 = J + 1;
        if (J1 == NT_ROW) { I1 = I + 1; J1 = I1; }
        bool havenext = (t + 1 < cnt);
        int apn = ap;
        if (havenext) {
            if (I1 != I) {
                apn = ap ^ 1;
                load_tile_async(sb + AS(apn), I1 * 128, tid);
            }
            if (J1 != I1) {
                load_tile_async(sb + BS((t + 1) & 1), J1 * 128, tid);
            }
            CP_COMMIT();
        }

        bool dt = (I == J);
        uint32_t a_addr = sb + AS(ap) + a_lane;
        uint32_t bbuf = (dt ? (sb + AS(ap)) : (sb + BS(t & 1))) + b_lane;

        float acc[2][4][4];
#pragma unroll
        for (int mt = 0; mt < 2; mt++)
#pragma unroll
            for (int nt = 0; nt < 4; nt++)
#pragma unroll
                for (int q = 0; q < 4; q++) acc[mt][nt][q] = 0.f;

        float rlo[2] = {0.f, 0.f}, rhi[2] = {0.f, 0.f};
        float cp0[4] = {0.f, 0.f, 0.f, 0.f}, cp1[4] = {0.f, 0.f, 0.f, 0.f};

#pragma unroll
        for (int ks = 0; ks < 8; ks++) {
            uint32_t koff = ks * 32;
            uint32_t a0[4], a1[4];
            ldsm4(a0[0], a0[1], a0[2], a0[3], a_addr + koff);
            ldsm4(a1[0], a1[1], a1[2], a1[3], a_addr + 16 * SAB + koff);
            uint32_t bfr[2][4];
#pragma unroll
            for (int p = 0; p < 2; p++)
                ldsm4(bfr[p][0], bfr[p][1], bfr[p][2], bfr[p][3],
                      bbuf + (p * 16) * SAB + koff);
#pragma unroll
            for (int nt = 0; nt < 4; nt++) {
                uint32_t bb0 = bfr[nt >> 1][(nt & 1) * 2];
                uint32_t bb1 = bfr[nt >> 1][(nt & 1) * 2 + 1];
                mma_fp8(acc[0][nt], a0[0], a0[1], a0[2], a0[3], bb0, bb1);
                mma_fp8(acc[1][nt], a1[0], a1[1], a1[2], a1[3], bb0, bb1);
            }
            if (t > 0) {
                int mt = ks & 1, nt = ks >> 1;
                int lr = lrl0 + mt * 16;
                int lc = lcb0 + nt * 8;
                float v0 = (dtp && lc == lr)         ? EXP_DIAG : ex2f(prev[mt][nt][0] * EXP_SCALE);
                float v1 = (dtp && lc + 1 == lr)     ? EXP_DIAG : ex2f(prev[mt][nt][1] * EXP_SCALE);
                float v2 = (dtp && lc == lr + 8)     ? EXP_DIAG : ex2f(prev[mt][nt][2] * EXP_SCALE);
                float v3 = (dtp && lc + 1 == lr + 8) ? EXP_DIAG : ex2f(prev[mt][nt][3] * EXP_SCALE);
                rlo[mt] += v0 + v1;
                rhi[mt] += v2 + v3;
                cp0[nt] += v0 + v2;
                cp1[nt] += v1 + v3;
            }
        }

        if (t > 0) {
            float* red_row = (float*)(smem + RED_OFF + ((t - 1) & 1) * RED_PAR);
            float* red_col = red_row + 512;
#pragma unroll
            for (int mt = 0; mt < 2; mt++) {
                rlo[mt] += __shfl_xor_sync(0xFFFFFFFF, rlo[mt], 1);
                rlo[mt] += __shfl_xor_sync(0xFFFFFFFF, rlo[mt], 2);
                rhi[mt] += __shfl_xor_sync(0xFFFFFFFF, rhi[mt], 1);
                rhi[mt] += __shfl_xor_sync(0xFFFFFFFF, rhi[mt], 2);
            }
#pragma unroll
            for (int nt = 0; nt < 4; nt++) {
                cp0[nt] += __shfl_xor_sync(0xFFFFFFFF, cp0[nt], 4);
                cp0[nt] += __shfl_xor_sync(0xFFFFFFFF, cp0[nt], 8);
                cp0[nt] += __shfl_xor_sync(0xFFFFFFFF, cp0[nt], 16);
                cp1[nt] += __shfl_xor_sync(0xFFFFFFFF, cp1[nt], 4);
                cp1[nt] += __shfl_xor_sync(0xFFFFFFFF, cp1[nt], 8);
                cp1[nt] += __shfl_xor_sync(0xFFFFFFFF, cp1[nt], 16);
            }
            if ((lane & 3) == 0) {
#pragma unroll
                for (int mt = 0; mt < 2; mt++) {
                    int r = wy * 32 + mt * 16 + (lane >> 2);
                    red_row[r * 4 + wx] = rlo[mt];
                    red_row[(r + 8) * 4 + wx] = rhi[mt];
                }
            }
            if (lane < 4) {
#pragma unroll
                for (int nt = 0; nt < 4; nt++) {
                    int c = wx * 32 + nt * 8 + lane * 2;
                    red_col[c * 4 + wy] = cp0[nt];
                    red_col[(c + 1) * 4 + wy] = cp1[nt];
                }
            }
        }
        if (havenext) CP_WAIT0();
        __syncthreads();
        if (t > 0 && tid < 128) {
            float* red_row = (float*)(smem + RED_OFF + ((t - 1) & 1) * RED_PAR);
            float* red_col = red_row + 512;
            float rz = (red_row[tid * 4] + red_row[tid * 4 + 1]) +
                       (red_row[tid * 4 + 2] + red_row[tid * 4 + 3]);
            g_Zp[(size_t)(Ip * 128 + tid) * NT_ROW + Jp] = rz;
            if (!dtp) {
                float cz = (red_col[tid * 4] + red_col[tid * 4 + 1]) +
                           (red_col[tid * 4 + 2] + red_col[tid * 4 + 3]);
                g_Zp[(size_t)(Jp * 128 + tid) * NT_ROW + Ip] = cz;
            }
        }

#pragma unroll
        for (int mt = 0; mt < 2; mt++)
#pragma unroll
            for (int nt = 0; nt < 4; nt++)
#pragma unroll
                for (int q = 0; q < 4; q++) prev[mt][nt][q] = acc[mt][nt][q];
        Ip = I; Jp = J; dtp = (I == J);
        I = I1; J = J1; ap = apn;
    }

    // final epilogue for last tile
    {
        float rlo[2] = {0.f, 0.f}, rhi[2] = {0.f, 0.f};
        float cp0[4] = {0.f, 0.f, 0.f, 0.f}, cp1[4] = {0.f, 0.f, 0.f, 0.f};
#pragma unroll
        for (int ks = 0; ks < 8; ks++) {
            int mt = ks & 1, nt = ks >> 1;
            int lr = lrl0 + mt * 16;
            int lc = lcb0 + nt * 8;
            float v0 = (dtp && lc == lr)         ? EXP_DIAG : ex2f(prev[mt][nt][0] * EXP_SCALE);
            float v1 = (dtp && lc + 1 == lr)     ? EXP_DIAG : ex2f(prev[mt][nt][1] * EXP_SCALE);
            float v2 = (dtp && lc == lr + 8)     ? EXP_DIAG : ex2f(prev[mt][nt][2] * EXP_SCALE);
            float v3 = (dtp && lc + 1 == lr + 8) ? EXP_DIAG : ex2f(prev[mt][nt][3] * EXP_SCALE);
            rlo[mt] += v0 + v1;
            rhi[mt] += v2 + v3;
            cp0[nt] += v0 + v2;
            cp1[nt] += v1 + v3;
        }
        float* red_row = (float*)(smem + RED_OFF + ((cnt - 1) & 1) * RED_PAR);
        float* red_col = red_row + 512;
#pragma unroll
        for (int mt = 0; mt < 2; mt++) {
            rlo[mt] += __shfl_xor_sync(0xFFFFFFFF, rlo[mt], 1);
            rlo[mt] += __shfl_xor_sync(0xFFFFFFFF, rlo[mt], 2);
            rhi[mt] += __shfl_xor_sync(0xFFFFFFFF, rhi[mt], 1);
            rhi[mt] += __shfl_xor_sync(0xFFFFFFFF, rhi[mt], 2);
        }
#pragma unroll
        for (int nt = 0; nt < 4; nt++) {
            cp0[nt] += __shfl_xor_sync(0xFFFFFFFF, cp0[nt], 4);
            cp0[nt] += __shfl_xor_sync(0xFFFFFFFF, cp0[nt], 8);
            cp0[nt] += __shfl_xor_sync(0xFFFFFFFF, cp0[nt], 16);
            cp1[nt] += __shfl_xor_sync(0xFFFFFFFF, cp1[nt], 4);
            cp1[nt] += __shfl_xor_sync(0xFFFFFFFF, cp1[nt], 8);
            cp1[nt] += __shfl_xor_sync(0xFFFFFFFF, cp1[nt], 16);
        }
        if ((lane & 3) == 0) {
#pragma unroll
            for (int mt = 0; mt < 2; mt++) {
                int r = wy * 32 + mt * 16 + (lane >> 2);
                red_row[r * 4 + wx] = rlo[mt];
                red_row[(r + 8) * 4 + wx] = rhi[mt];
            }
        }
        if (lane < 4) {
#pragma unroll
            for (int nt = 0; nt < 4; nt++) {
                int c = wx * 32 + nt * 8 + lane * 2;
                red_col[c * 4 + wy] = cp0[nt];
                red_col[(c + 1) * 4 + wy] = cp1[nt];
            }
        }
        __syncthreads();
        if (tid < 128) {
            float rz = (red_row[tid * 4] + red_row[tid * 4 + 1]) +
                       (red_row[tid * 4 + 2] + red_row[tid * 4 + 3]);
            g_Zp[(size_t)(Ip * 128 + tid) * NT_ROW + Jp] = rz;
            if (!dtp) {
                float cz = (red_col[tid * 4] + red_col[tid * 4 + 1]) +
                           (red_col[tid * 4 + 2] + red_col[tid * 4 + 3]);
                g_Zp[(size_t)(Jp * 128 + tid) * NT_ROW + Ip] = cz;
            }
        }
    }

    // ---- class-sum finalize in the end-slack of two 14-tile CTAs -------------------
    // bid 100/101 finish ~5.4us before the 15-tile CTAs; partials were written and
    // __threadfence'd by the side-job CTAs ~70us earlier (L1 launch-flushed => reads
    // fetch from coherent L2). Deterministic chunk order.
    if (bid == 100 || bid == 101) {
        int half = bid - 100;
        for (int item = half * 1024 + tid; item < half * 1024 + 1024; item += 512) {
            int c = item >> 8, d = item & 255;
            float s = 0.f;
            for (int b = 0; b < NCHUNK; b++) s += g_clsum_part[(b * CLS + c) * DIM + d];
            g_clsum[c * DIM + d] = s;
        }
        if (bid == 100 && tid < CLS) {
            float cn = 0.f;
            for (int b = 0; b < NCHUNK; b++) cn += g_clcnt_part[b * CLS + tid];
            g_clcnt[tid] = cn;
        }
    }
}

// ---------------- 3) per-row contrastive: one wave, pipelined rows -------------------
__global__ void __launch_bounds__(512) k_con(const int* __restrict__ tgt) {
    int wid = threadIdx.x >> 5, lane = threadIdx.x & 31;
    int row = blockIdx.x * 16 + wid;
    if (row >= N) return;

    int t = tgt[row];
    float z0 = g_Zp[(size_t)row * NT_ROW + lane];
    float z1 = g_Zp[(size_t)row * NT_ROW + lane + 32];
    uint2 q = *(const uint2*)(g_embq + (size_t)row * 128 + lane * 4);

    while (row < N) {
        int nrow = row + NORM_WARPS;
        int tn = 0;
        float nz0 = 0.f, nz1 = 0.f;
        uint2 nq = make_uint2(0u, 0u);
        if (nrow < N) {                 // prefetch next row before current reduction
            tn = tgt[nrow];
            nz0 = g_Zp[(size_t)nrow * NT_ROW + lane];
            nz1 = g_Zp[(size_t)nrow * NT_ROW + lane + 32];
            nq = *(const uint2*)(g_embq + (size_t)nrow * 128 + lane * 4);
        }

        const float4* sc = (const float4*)&g_clsum[t * DIM];
        float4 c0 = sc[lane * 2], c1 = sc[lane * 2 + 1];
        float2 e0 = e4m3x2_to_f2(q.x & 0xFFFFu);
        float2 e1 = e4m3x2_to_f2(q.x >> 16);
        float2 e2 = e4m3x2_to_f2(q.y & 0xFFFFu);
        float2 e3 = e4m3x2_to_f2(q.y >> 16);

        float dot = e0.x * c0.x + e0.y * c0.y + e1.x * c0.z + e1.y * c0.w +
                    e2.x * c1.x + e2.y * c1.y + e3.x * c1.z + e3.y * c1.w;
        float zs = z0 + z1;
#pragma unroll
        for (int off = 16; off > 0; off >>= 1) {
            dot += __shfl_xor_sync(0xFFFFFFFF, dot, off);
            zs += __shfl_xor_sync(0xFFFFFFFF, zs, off);
        }
        if (lane == 0) {
            float logZ = logf(zs + 1e-8f);
            float npos = g_clcnt[t] - 1.0f;
            float msum = (dot - 1.0f) * INV_T;
            g_con[row] = (npos * logZ - msum) / fmaxf(npos, 1.0f);
        }

        row = nrow; t = tn; z0 = nz0; z1 = nz1; q = nq;
    }
}

// ---------------- 4) final reduction -------------------------------------------------
__global__ void k_final(float* __restrict__ out, int out_size) {
    __shared__ float s[256];
    int t = threadIdx.x;

    float cs = 0.f;
    for (int i = t; i < N; i += 256) cs += g_con[i];
    s[t] = cs;
    __syncthreads();
    for (int off = 128; off > 0; off >>= 1) {
        if (t < off) s[t] += s[t + off];
        __syncthreads();
    }
    __shared__ float con_sum;
    if (t == 0) con_sum = s[0];
    __syncthreads();

    s[t] = g_ce_part[t];
    __syncthreads();
    for (int off = 128; off > 0; off >>= 1) {
        if (t < off) s[t] += s[t + off];
        __syncthreads();
    }
    if (t == 0) {
        float ce_mean = s[0] * (1.0f / N);
        float con_mean = con_sum * (1.0f / N);
        out[0] = ce_mean + ALPHA * con_mean;
        if (out_size > 1) out[1] = ce_mean;
        if (out_size > 2) out[2] = con_mean;
    }
}

// ---------------- launcher ----------------------------------------------------------
extern "C" void kernel_launch(void* const* d_in, const int* in_sizes, int n_in,
                              void* d_out, int out_size) {
    const float* logits = (const float*)d_in[0];
    const float* emb = (const float*)d_in[1];
    const int* tgt = (const int*)d_in[2];
    float* out = (float*)d_out;

    cudaFuncSetAttribute(k_sim_sym, cudaFuncAttributeMaxDynamicSharedMemorySize, SMEM_TOTAL);

    k_norm<<<148, 512>>>(emb);
    k_sim_sym<<<148, 512, SMEM_TOTAL>>>(logits, tgt);
    k_con<<<148, 512>>>(tgt);
    k_final<<<1, 256>>>(out, out_size);
}